// round 5
// baseline (speedup 1.0000x reference)
#include <cuda_runtime.h>

#define B  4
#define T  1024
#define DM 512
#define NH 8
#define DK 64

// ---------------- scratch (device globals; no allocs allowed) ----------------
__device__ float g_Q[B * NH * T * DK];
__device__ float g_K[B * NH * T * DK];
__device__ float g_V[B * NH * T * DK];
__device__ float g_M[(size_t)B * NH * T * T];
__device__ float g_Mt[(size_t)B * NH * T * T];
__device__ float g_Ctx[B * T * DM];

// packed f32x2 FMA (PTX-only; ptxas never auto-fuses this)
union F2U { float2 f; unsigned long long u; };
__device__ __forceinline__ void ffma2(float2& c, float2 a, float2 b) {
    F2U A, Bv, C;
    A.f = a; Bv.f = b; C.f = c;
    asm("fma.rn.f32x2 %0, %1, %2, %0;" : "+l"(C.u) : "l"(A.u), "l"(Bv.u));
    c = C.f;
}

// =============================================================================
// Division-free halo tile loader for one channel plane.
// smem row layout (72 floats, 288B): col j <-> global x0-4+j.
//   body  x0..x0+63  at j=4..67  (STS.128, 16B aligned)
//   left  x0-1       at j=3
//   right x0+64      at j=68
// Rows r=0..17 <-> y0-1..y0+16.
// =============================================================================
__device__ __forceinline__ void load_halo_tile(float* __restrict__ sdst,
                                               const float* __restrict__ src,
                                               int y0, int x0) {
    int tid = threadIdx.x;
    #pragma unroll
    for (int step = 0; step < 2; step++) {
        int slot = step * 256 + tid;
        if (slot < 288) {                      // body: r = slot>>4, q = slot&15
            int r = slot >> 4, qq = slot & 15;
            int y = y0 - 1 + r;
            float4 v = make_float4(0.f, 0.f, 0.f, 0.f);
            if (y >= 0 && y < T) v = *(const float4*)&src[(size_t)y * T + x0 + qq * 4];
            *(float4*)&sdst[r * 72 + 4 + qq * 4] = v;
        } else if (slot < 306) {               // left halo
            int r = slot - 288;
            int y = y0 - 1 + r, x = x0 - 1;
            float v = 0.f;
            if (y >= 0 && y < T && x >= 0) v = src[(size_t)y * T + x];
            sdst[r * 72 + 3] = v;
        } else if (slot < 324) {               // right halo
            int r = slot - 306;
            int y = y0 - 1 + r, x = x0 + 64;
            float v = 0.f;
            if (y >= 0 && y < T && x < T) v = src[(size_t)y * T + x];
            sdst[r * 72 + 68] = v;
        }
    }
}

// =============================================================================
// QKV projections: one launch, z = 0/1/2 selects (q,w_q)->g_Q etc.
// =============================================================================
__global__ void __launch_bounds__(256) gemm_qkv(const float* __restrict__ q,
                                                const float* __restrict__ k,
                                                const float* __restrict__ v,
                                                const float* __restrict__ w_q,
                                                const float* __restrict__ w_k,
                                                const float* __restrict__ w_v) {
    __shared__ float As[32][132];
    __shared__ float Ws[32][68];

    int z = blockIdx.z;
    const float* A = (z == 0) ? q : (z == 1) ? k : v;
    const float* W = (z == 0) ? w_q : (z == 1) ? w_k : w_v;
    float* C = (z == 0) ? g_Q : (z == 1) ? g_K : g_V;

    int m0 = blockIdx.y * 128;
    int n0 = blockIdx.x * 64;
    int tid = threadIdx.x;
    int tx = tid & 15, ty = tid >> 4;
    int rb = tid >> 3, kk = (tid & 7) * 4;

    float2 acc[8][2];
    #pragma unroll
    for (int i = 0; i < 8; i++) { acc[i][0] = make_float2(0.f, 0.f); acc[i][1] = make_float2(0.f, 0.f); }

    for (int k0 = 0; k0 < 512; k0 += 32) {
        #pragma unroll
        for (int i = 0; i < 4; i++) {
            float4 t4 = *(const float4*)&A[(size_t)(m0 + rb + i * 32) * 512 + k0 + kk];
            As[kk + 0][rb + i * 32] = t4.x; As[kk + 1][rb + i * 32] = t4.y;
            As[kk + 2][rb + i * 32] = t4.z; As[kk + 3][rb + i * 32] = t4.w;
        }
        #pragma unroll
        for (int i = 0; i < 2; i++) {
            float4 t4 = *(const float4*)&W[(size_t)(n0 + rb + i * 32) * 512 + k0 + kk];
            Ws[kk + 0][rb + i * 32] = t4.x; Ws[kk + 1][rb + i * 32] = t4.y;
            Ws[kk + 2][rb + i * 32] = t4.z; Ws[kk + 3][rb + i * 32] = t4.w;
        }
        __syncthreads();
        #pragma unroll
        for (int kx = 0; kx < 32; kx++) {
            float4 a0 = *(float4*)&As[kx][ty * 8];
            float4 a1 = *(float4*)&As[kx][ty * 8 + 4];
            float4 b4 = *(float4*)&Ws[kx][tx * 4];
            float2 b0 = make_float2(b4.x, b4.y), b1 = make_float2(b4.z, b4.w);
            float av[8] = {a0.x, a0.y, a0.z, a0.w, a1.x, a1.y, a1.z, a1.w};
            #pragma unroll
            for (int i = 0; i < 8; i++) {
                float2 ad = make_float2(av[i], av[i]);
                ffma2(acc[i][0], ad, b0);
                ffma2(acc[i][1], ad, b1);
            }
        }
        __syncthreads();
    }

    int h = n0 >> 6;
    #pragma unroll
    for (int i = 0; i < 8; i++) {
        int row = m0 + ty * 8 + i;
        int b = row >> 10, t = row & 1023;
        float4 o = make_float4(acc[i][0].x, acc[i][0].y, acc[i][1].x, acc[i][1].y);
        *(float4*)&C[(size_t)((b * NH + h) * T + t) * DK + tx * 4] = o;
    }
}

// =============================================================================
// Output projection: out = g_Ctx @ w_o^T
// =============================================================================
__global__ void __launch_bounds__(256) gemm_wo(const float* __restrict__ W,
                                               float* __restrict__ out) {
    __shared__ float As[32][132];
    __shared__ float Ws[32][68];

    int m0 = blockIdx.y * 128;
    int n0 = blockIdx.x * 64;
    int tid = threadIdx.x;
    int tx = tid & 15, ty = tid >> 4;
    int rb = tid >> 3, kk = (tid & 7) * 4;

    float2 acc[8][2];
    #pragma unroll
    for (int i = 0; i < 8; i++) { acc[i][0] = make_float2(0.f, 0.f); acc[i][1] = make_float2(0.f, 0.f); }

    for (int k0 = 0; k0 < 512; k0 += 32) {
        #pragma unroll
        for (int i = 0; i < 4; i++) {
            float4 t4 = *(const float4*)&g_Ctx[(size_t)(m0 + rb + i * 32) * 512 + k0 + kk];
            As[kk + 0][rb + i * 32] = t4.x; As[kk + 1][rb + i * 32] = t4.y;
            As[kk + 2][rb + i * 32] = t4.z; As[kk + 3][rb + i * 32] = t4.w;
        }
        #pragma unroll
        for (int i = 0; i < 2; i++) {
            float4 t4 = *(const float4*)&W[(size_t)(n0 + rb + i * 32) * 512 + k0 + kk];
            Ws[kk + 0][rb + i * 32] = t4.x; Ws[kk + 1][rb + i * 32] = t4.y;
            Ws[kk + 2][rb + i * 32] = t4.z; Ws[kk + 3][rb + i * 32] = t4.w;
        }
        __syncthreads();
        #pragma unroll
        for (int kx = 0; kx < 32; kx++) {
            float4 a0 = *(float4*)&As[kx][ty * 8];
            float4 a1 = *(float4*)&As[kx][ty * 8 + 4];
            float4 b4 = *(float4*)&Ws[kx][tx * 4];
            float2 b0 = make_float2(b4.x, b4.y), b1 = make_float2(b4.z, b4.w);
            float av[8] = {a0.x, a0.y, a0.z, a0.w, a1.x, a1.y, a1.z, a1.w};
            #pragma unroll
            for (int i = 0; i < 8; i++) {
                float2 ad = make_float2(av[i], av[i]);
                ffma2(acc[i][0], ad, b0);
                ffma2(acc[i][1], ad, b1);
            }
        }
        __syncthreads();
    }

    #pragma unroll
    for (int i = 0; i < 8; i++) {
        int row = m0 + ty * 8 + i;
        float4 o = make_float4(acc[i][0].x, acc[i][0].y, acc[i][1].x, acc[i][1].y);
        *(float4*)&out[(size_t)row * 512 + n0 + tx * 4] = o;
    }
}

// =============================================================================
// M = Q K^T per (b,h).  128x64 tile, DK=64 in two 32-chunks.
// =============================================================================
__global__ void __launch_bounds__(256) qk_kernel() {
    __shared__ float Qs[32][132];
    __shared__ float Ks[32][68];

    int bh = blockIdx.z;
    const float* Qb = g_Q + (size_t)bh * T * DK;
    const float* Kb = g_K + (size_t)bh * T * DK;
    int q0 = blockIdx.y * 128;
    int k0 = blockIdx.x * 64;
    int tid = threadIdx.x;
    int tx = tid & 15, ty = tid >> 4;
    int rb = tid >> 3, kk = (tid & 7) * 4;

    float2 acc[8][2];
    #pragma unroll
    for (int i = 0; i < 8; i++) { acc[i][0] = make_float2(0.f, 0.f); acc[i][1] = make_float2(0.f, 0.f); }

    for (int d0 = 0; d0 < 64; d0 += 32) {
        #pragma unroll
        for (int i = 0; i < 4; i++) {
            float4 t4 = *(const float4*)&Qb[(size_t)(q0 + rb + i * 32) * DK + d0 + kk];
            Qs[kk + 0][rb + i * 32] = t4.x; Qs[kk + 1][rb + i * 32] = t4.y;
            Qs[kk + 2][rb + i * 32] = t4.z; Qs[kk + 3][rb + i * 32] = t4.w;
        }
        #pragma unroll
        for (int i = 0; i < 2; i++) {
            float4 t4 = *(const float4*)&Kb[(size_t)(k0 + rb + i * 32) * DK + d0 + kk];
            Ks[kk + 0][rb + i * 32] = t4.x; Ks[kk + 1][rb + i * 32] = t4.y;
            Ks[kk + 2][rb + i * 32] = t4.z; Ks[kk + 3][rb + i * 32] = t4.w;
        }
        __syncthreads();
        #pragma unroll
        for (int kx = 0; kx < 32; kx++) {
            float4 a0 = *(float4*)&Qs[kx][ty * 8];
            float4 a1 = *(float4*)&Qs[kx][ty * 8 + 4];
            float4 b4 = *(float4*)&Ks[kx][tx * 4];
            float2 b0 = make_float2(b4.x, b4.y), b1 = make_float2(b4.z, b4.w);
            float av[8] = {a0.x, a0.y, a0.z, a0.w, a1.x, a1.y, a1.z, a1.w};
            #pragma unroll
            for (int i = 0; i < 8; i++) {
                float2 ad = make_float2(av[i], av[i]);
                ffma2(acc[i][0], ad, b0);
                ffma2(acc[i][1], ad, b1);
            }
        }
        __syncthreads();
    }

    float* Mb = g_M + (size_t)bh * T * T;
    #pragma unroll
    for (int i = 0; i < 8; i++) {
        float4 o = make_float4(acc[i][0].x, acc[i][0].y, acc[i][1].x, acc[i][1].y);
        *(float4*)&Mb[(size_t)(q0 + ty * 8 + i) * T + k0 + tx * 4] = o;
    }
}

// =============================================================================
// Mt = conv3x3(prev, tw) + tb  (8 -> 8 ch). 64x16 tile, 4 px/thread.
// =============================================================================
__global__ void __launch_bounds__(256) conv_mt(const float* __restrict__ prev,
                                               const float* __restrict__ tw,
                                               const float* __restrict__ tb) {
    __shared__ float s[8][18 * 72];
    __shared__ float4 swt[8 * 9 * 2];   // [(c*9+t9)*2 + half] -> o0..3 / o4..7
    __shared__ float sb[8];

    int b = blockIdx.z;
    int x0 = blockIdx.x * 64;
    int y0 = blockIdx.y * 16;
    int tid = threadIdx.x;
    int tx = tid & 15, ty = tid >> 4;

    for (int e = tid; e < 576; e += 256) {
        int o = e / 72, rem = e - o * 72;           // rem = c*9+t9
        ((float*)swt)[rem * 8 + o] = tw[e];
    }
    if (tid < 8) sb[tid] = tb[tid];

    #pragma unroll
    for (int c = 0; c < 8; c++)
        load_halo_tile(s[c], prev + (size_t)(b * 8 + c) * T * T, y0, x0);
    __syncthreads();

    float2 acc[4][4];
    #pragma unroll
    for (int p = 0; p < 4; p++)
        #pragma unroll
        for (int o2 = 0; o2 < 4; o2++)
            acc[p][o2] = make_float2(sb[o2 * 2], sb[o2 * 2 + 1]);

    int cx = tx * 4;
    #pragma unroll
    for (int c = 0; c < 8; c++) {
        const float* sc = &s[c][ty * 72 + cx + 3];
        float v[3][6];
        #pragma unroll
        for (int dy = 0; dy < 3; dy++) {
            v[dy][0] = sc[dy * 72];
            float4 m = *(const float4*)(sc + dy * 72 + 1);
            v[dy][1] = m.x; v[dy][2] = m.y; v[dy][3] = m.z; v[dy][4] = m.w;
            v[dy][5] = sc[dy * 72 + 5];
        }
        #pragma unroll
        for (int dy = 0; dy < 3; dy++) {
            #pragma unroll
            for (int dx = 0; dx < 3; dx++) {
                int t9 = dy * 3 + dx;
                float4 wA = swt[(c * 9 + t9) * 2];
                float4 wB = swt[(c * 9 + t9) * 2 + 1];
                float2 w0 = make_float2(wA.x, wA.y), w1 = make_float2(wA.z, wA.w);
                float2 w2 = make_float2(wB.x, wB.y), w3 = make_float2(wB.z, wB.w);
                #pragma unroll
                for (int p = 0; p < 4; p++) {
                    float vv = v[dy][dx + p];
                    float2 vd = make_float2(vv, vv);
                    ffma2(acc[p][0], vd, w0);
                    ffma2(acc[p][1], vd, w1);
                    ffma2(acc[p][2], vd, w2);
                    ffma2(acc[p][3], vd, w3);
                }
            }
        }
    }

    int y = y0 + ty;
    #pragma unroll
    for (int o = 0; o < 8; o++) {
        int o2 = o >> 1;
        float4 ov;
        if (o & 1) ov = make_float4(acc[0][o2].y, acc[1][o2].y, acc[2][o2].y, acc[3][o2].y);
        else       ov = make_float4(acc[0][o2].x, acc[1][o2].x, acc[2][o2].x, acc[3][o2].x);
        *(float4*)&g_Mt[((size_t)(b * 8 + o) * T + y) * T + x0 + cx] = ov;
    }
}

// =============================================================================
// Apre = (conv3x3(concat(M, Mt), aw) + ab) / 8, masked. Writes A into d_out.
// =============================================================================
__global__ void __launch_bounds__(256) conv_ma(const float* __restrict__ aw,
                                               const float* __restrict__ ab,
                                               const int* __restrict__ mask,
                                               float* __restrict__ Apre) {
    __shared__ float s[8][18 * 72];
    __shared__ float4 swa[16 * 9 * 2];  // [(c*9+t9)*2 + half]
    __shared__ float sab[8];

    int b = blockIdx.z;
    int x0 = blockIdx.x * 64;
    int y0 = blockIdx.y * 16;
    int tid = threadIdx.x;
    int tx = tid & 15, ty = tid >> 4;

    for (int e = tid; e < 1152; e += 256) {
        int o = e / 144, rem = e - o * 144;         // rem = c*9+t9
        ((float*)swa)[rem * 8 + o] = aw[e];
    }
    if (tid < 8) sab[tid] = ab[tid];

    float2 acc[4][4];
    #pragma unroll
    for (int p = 0; p < 4; p++)
        #pragma unroll
        for (int o2 = 0; o2 < 4; o2++)
            acc[p][o2] = make_float2(0.f, 0.f);

    int cx = tx * 4;

    #pragma unroll
    for (int pass = 0; pass < 2; pass++) {
        const float* src = pass ? g_Mt : g_M;
        #pragma unroll
        for (int c = 0; c < 8; c++)
            load_halo_tile(s[c], src + (size_t)(b * 8 + c) * T * T, y0, x0);
        __syncthreads();

        #pragma unroll
        for (int c = 0; c < 8; c++) {
            int cw = c + pass * 8;
            const float* sc = &s[c][ty * 72 + cx + 3];
            float v[3][6];
            #pragma unroll
            for (int dy = 0; dy < 3; dy++) {
                v[dy][0] = sc[dy * 72];
                float4 m = *(const float4*)(sc + dy * 72 + 1);
                v[dy][1] = m.x; v[dy][2] = m.y; v[dy][3] = m.z; v[dy][4] = m.w;
                v[dy][5] = sc[dy * 72 + 5];
            }
            #pragma unroll
            for (int dy = 0; dy < 3; dy++) {
                #pragma unroll
                for (int dx = 0; dx < 3; dx++) {
                    int t9 = dy * 3 + dx;
                    float4 wA = swa[(cw * 9 + t9) * 2];
                    float4 wB = swa[(cw * 9 + t9) * 2 + 1];
                    float2 w0 = make_float2(wA.x, wA.y), w1 = make_float2(wA.z, wA.w);
                    float2 w2 = make_float2(wB.x, wB.y), w3 = make_float2(wB.z, wB.w);
                    #pragma unroll
                    for (int p = 0; p < 4; p++) {
                        float vv = v[dy][dx + p];
                        float2 vd = make_float2(vv, vv);
                        ffma2(acc[p][0], vd, w0);
                        ffma2(acc[p][1], vd, w1);
                        ffma2(acc[p][2], vd, w2);
                        ffma2(acc[p][3], vd, w3);
                    }
                }
            }
        }
        if (pass == 0) __syncthreads();
    }

    int y = y0 + ty;
    int xg = x0 + cx;
    bool mk[4];
    #pragma unroll
    for (int p = 0; p < 4; p++) mk[p] = (mask[b * T + xg + p] == 0);

    #pragma unroll
    for (int o = 0; o < 8; o++) {
        int o2 = o >> 1;
        float r0, r1, r2, r3;
        if (o & 1) { r0 = acc[0][o2].y; r1 = acc[1][o2].y; r2 = acc[2][o2].y; r3 = acc[3][o2].y; }
        else       { r0 = acc[0][o2].x; r1 = acc[1][o2].x; r2 = acc[2][o2].x; r3 = acc[3][o2].x; }
        float bias = sab[o];
        r0 = (r0 + bias) * 0.125f; r1 = (r1 + bias) * 0.125f;
        r2 = (r2 + bias) * 0.125f; r3 = (r3 + bias) * 0.125f;
        if (mk[0]) r0 = -1e9f;
        if (mk[1]) r1 = -1e9f;
        if (mk[2]) r2 = -1e9f;
        if (mk[3]) r3 = -1e9f;
        float4 ov = make_float4(r0, r1, r2, r3);
        *(float4*)&Apre[((size_t)(b * 8 + o) * T + y) * T + xg] = ov;
    }
}

// ---------------- in-place row softmax (rows of 1024) ------------------------
__global__ void __launch_bounds__(256) softmax_kernel(float* __restrict__ A) {
    __shared__ float red[8];
    int row = blockIdx.x;
    float* p = A + (size_t)row * 1024;
    int tid = threadIdx.x;

    float4 v = *(float4*)&p[tid * 4];

    float mx = fmaxf(fmaxf(v.x, v.y), fmaxf(v.z, v.w));
    #pragma unroll
    for (int o = 16; o > 0; o >>= 1) mx = fmaxf(mx, __shfl_xor_sync(~0u, mx, o));
    if ((tid & 31) == 0) red[tid >> 5] = mx;
    __syncthreads();
    mx = red[0];
    #pragma unroll
    for (int i = 1; i < 8; i++) mx = fmaxf(mx, red[i]);
    __syncthreads();

    v.x = __expf(v.x - mx); v.y = __expf(v.y - mx);
    v.z = __expf(v.z - mx); v.w = __expf(v.w - mx);
    float s = v.x + v.y + v.z + v.w;
    #pragma unroll
    for (int o = 16; o > 0; o >>= 1) s += __shfl_xor_sync(~0u, s, o);
    if ((tid & 31) == 0) red[tid >> 5] = s;
    __syncthreads();
    s = 0.f;
    #pragma unroll
    for (int i = 0; i < 8; i++) s += red[i];
    float inv = 1.f / s;

    v.x *= inv; v.y *= inv; v.z *= inv; v.w *= inv;
    *(float4*)&p[tid * 4] = v;
}

// =============================================================================
// Ctx = A @ V per (b,h). 128x64 tile, K-chunks of 32 over 1024.
// =============================================================================
__global__ void __launch_bounds__(256) av_kernel(const float* __restrict__ A) {
    __shared__ float As[32][132];
    __shared__ float Vs[32][68];

    int bh = blockIdx.y;
    int b = bh >> 3, h = bh & 7;
    const float* Ab = A + (size_t)bh * T * T;
    const float* Vb = g_V + (size_t)bh * T * DK;
    int q0 = blockIdx.x * 128;
    int tid = threadIdx.x;
    int tx = tid & 15, ty = tid >> 4;
    int rb = tid >> 3, kk = (tid & 7) * 4;
    int vd = (tid & 15) * 4, vk = tid >> 4;

    float2 acc[8][2];
    #pragma unroll
    for (int i = 0; i < 8; i++) { acc[i][0] = make_float2(0.f, 0.f); acc[i][1] = make_float2(0.f, 0.f); }

    for (int kc = 0; kc < T; kc += 32) {
        #pragma unroll
        for (int i = 0; i < 4; i++) {
            float4 t4 = *(const float4*)&Ab[(size_t)(q0 + rb + i * 32) * T + kc + kk];
            As[kk + 0][rb + i * 32] = t4.x; As[kk + 1][rb + i * 32] = t4.y;
            As[kk + 2][rb + i * 32] = t4.z; As[kk + 3][rb + i * 32] = t4.w;
        }
        #pragma unroll
        for (int i = 0; i < 2; i++) {
            float4 t4 = *(const float4*)&Vb[(size_t)(kc + vk + i * 16) * DK + vd];
            *(float4*)&Vs[vk + i * 16][vd] = t4;
        }
        __syncthreads();
        #pragma unroll
        for (int kx = 0; kx < 32; kx++) {
            float4 a0 = *(float4*)&As[kx][ty * 8];
            float4 a1 = *(float4*)&As[kx][ty * 8 + 4];
            float4 b4 = *(float4*)&Vs[kx][tx * 4];
            float2 b0 = make_float2(b4.x, b4.y), b1 = make_float2(b4.z, b4.w);
            float av[8] = {a0.x, a0.y, a0.z, a0.w, a1.x, a1.y, a1.z, a1.w};
            #pragma unroll
            for (int i = 0; i < 8; i++) {
                float2 ad = make_float2(av[i], av[i]);
                ffma2(acc[i][0], ad, b0);
                ffma2(acc[i][1], ad, b1);
            }
        }
        __syncthreads();
    }

    #pragma unroll
    for (int i = 0; i < 8; i++) {
        int qrow = q0 + ty * 8 + i;
        float4 o = make_float4(acc[i][0].x, acc[i][0].y, acc[i][1].x, acc[i][1].y);
        *(float4*)&g_Ctx[(size_t)(b * T + qrow) * DM + h * DK + tx * 4] = o;
    }
}

// ---------------- launcher ---------------------------------------------------
extern "C" void kernel_launch(void* const* d_in, const int* in_sizes, int n_in,
                              void* d_out, int out_size) {
    const float* q    = (const float*)d_in[0];
    const float* k    = (const float*)d_in[1];
    const float* v    = (const float*)d_in[2];
    const int*   mask = (const int*)  d_in[3];
    const float* prev = (const float*)d_in[4];
    const float* w_q  = (const float*)d_in[5];
    const float* w_k  = (const float*)d_in[6];
    const float* w_v  = (const float*)d_in[7];
    const float* w_o  = (const float*)d_in[8];
    const float* tw   = (const float*)d_in[9];
    const float* tb   = (const float*)d_in[10];
    const float* aw   = (const float*)d_in[11];
    const float* ab   = (const float*)d_in[12];

    float* out  = (float*)d_out;
    float* Aout = out + (size_t)B * T * DM;

    gemm_qkv<<<dim3(DM / 64, (B * T) / 128, 3), 256>>>(q, k, v, w_q, w_k, w_v);
    conv_mt<<<dim3(T / 64, T / 16, B), 256>>>(prev, tw, tb);
    qk_kernel<<<dim3(T / 64, T / 128, B * NH), 256>>>();
    conv_ma<<<dim3(T / 64, T / 16, B), 256>>>(aw, ab, mask, Aout);
    softmax_kernel<<<B * NH * T, 256>>>(Aout);
    av_kernel<<<dim3(T / 128, B * NH), 256>>>(Aout);
    gemm_wo<<<dim3(DM / 64, (B * T) / 128), 256>>>(w_o, out);
}

// round 7
// speedup vs baseline: 1.6509x; 1.6509x over previous
#include <cuda_runtime.h>
#include <cstdint>

#define B  4
#define T  1024
#define DM 512
#define NH 8
#define DK 64

// ---------------- scratch (device globals; no allocs allowed) ----------------
__device__ float g_Q[B * NH * T * DK];
__device__ float g_K[B * NH * T * DK];
__device__ float g_V[B * NH * T * DK];
__device__ float g_M[(size_t)B * NH * T * T];
__device__ float g_Mt[(size_t)B * NH * T * T];
__device__ float g_Ctx[B * T * DM];

// packed f32x2 FMA (PTX-only) — used by the conv kernels
union F2U { float2 f; unsigned long long u; };
__device__ __forceinline__ void ffma2(float2& c, float2 a, float2 b) {
    F2U A, Bv, C;
    A.f = a; Bv.f = b; C.f = c;
    asm("fma.rn.f32x2 %0, %1, %2, %0;" : "+l"(C.u) : "l"(A.u), "l"(Bv.u));
    c = C.f;
}

// =============================================================================
// Tensor-core building blocks: split-TF32 (3xTF32) m16n8k8 MMA
// =============================================================================
__device__ __forceinline__ void split_tf32(float x, uint32_t& hi, uint32_t& lo) {
    asm("cvt.rna.tf32.f32 %0, %1;" : "=r"(hi) : "f"(x));
    float l = x - __uint_as_float(hi);
    asm("cvt.rna.tf32.f32 %0, %1;" : "=r"(lo) : "f"(l));
}

__device__ __forceinline__ void mma_tf32(float* c, const uint32_t* a, const uint32_t* b) {
    asm("mma.sync.aligned.m16n8k8.row.col.f32.tf32.tf32.f32 "
        "{%0,%1,%2,%3}, {%4,%5,%6,%7}, {%8,%9}, {%0,%1,%2,%3};"
        : "+f"(c[0]), "+f"(c[1]), "+f"(c[2]), "+f"(c[3])
        : "r"(a[0]), "r"(a[1]), "r"(a[2]), "r"(a[3]), "r"(b[0]), "r"(b[1]));
}

#define LDSS 36   // smem row stride (floats) for 32-wide k tiles (+4 pad)

// Load a ROWS x 32 tile (row-major, leading dim ld) into smem [row][k] w/ stride LDSS
template<int ROWS>
__device__ __forceinline__ void load_tile(float* S, const float* src, int ld) {
    int t = threadIdx.x;
    int r = t >> 3, c4 = (t & 7) * 4;
    #pragma unroll
    for (int i = 0; i < ROWS / 32; i++) {
        float4 v = *(const float4*)&src[(size_t)(r + i * 32) * ld + c4];
        *(float4*)&S[(r + i * 32) * LDSS + c4] = v;
    }
}

// One 32-deep k-chunk of 3xTF32 MMAs.
// A smem: [m][k] stride LDSS. B smem: if BK==0: [n][k] stride LDSS; if BK==1: [k][n] stride 68.
template<int MT, int NT, int BK>
__device__ __forceinline__ void mma_chunk(const float* As, const float* Bs,
                                          int mbase, int nbase, float acc[][4]) {
    int lane = threadIdx.x & 31;
    int g = lane >> 2, t4 = lane & 3;
    #pragma unroll
    for (int k8 = 0; k8 < 4; k8++) {
        const int k0 = k8 * 8;
        uint32_t bhi[NT][2], blo[NT][2];
        #pragma unroll
        for (int nt = 0; nt < NT; nt++) {
            float b0, b1;
            if (BK == 0) {
                const float* bp = Bs + (nbase + nt * 8 + g) * LDSS + k0 + t4;
                b0 = bp[0]; b1 = bp[4];
            } else {
                const float* bp = Bs + (k0 + t4) * 68 + nbase + nt * 8 + g;
                b0 = bp[0]; b1 = bp[4 * 68];
            }
            split_tf32(b0, bhi[nt][0], blo[nt][0]);
            split_tf32(b1, bhi[nt][1], blo[nt][1]);
        }
        #pragma unroll
        for (int mt = 0; mt < MT; mt++) {
            const float* ap = As + (mbase + mt * 16 + g) * LDSS + k0 + t4;
            uint32_t ahi[4], alo[4];
            split_tf32(ap[0],             ahi[0], alo[0]);
            split_tf32(ap[8 * LDSS],      ahi[1], alo[1]);
            split_tf32(ap[4],             ahi[2], alo[2]);
            split_tf32(ap[8 * LDSS + 4],  ahi[3], alo[3]);
            #pragma unroll
            for (int nt = 0; nt < NT; nt++) {
                float* c = acc[mt * NT + nt];
                mma_tf32(c, ahi, bhi[nt]);
                mma_tf32(c, ahi, blo[nt]);
                mma_tf32(c, alo, bhi[nt]);
            }
        }
    }
}

// =============================================================================
// QKV projections (tensor): C = X @ W^T, scatter to (B,H,T,DK). 128x128 tiles.
// =============================================================================
__global__ void __launch_bounds__(256) tgemm_qkv(const float* __restrict__ q,
                                                 const float* __restrict__ k,
                                                 const float* __restrict__ v,
                                                 const float* __restrict__ w_q,
                                                 const float* __restrict__ w_k,
                                                 const float* __restrict__ w_v) {
    __shared__ float As[128 * LDSS];
    __shared__ float Bs[128 * LDSS];

    int z = blockIdx.z;
    const float* A = (z == 0) ? q : (z == 1) ? k : v;
    const float* W = (z == 0) ? w_q : (z == 1) ? w_k : w_v;
    float* C = (z == 0) ? g_Q : (z == 1) ? g_K : g_V;

    int m0 = blockIdx.y * 128, n0 = blockIdx.x * 128;
    int wid = threadIdx.x >> 5;
    int mbase = (wid >> 2) * 64, nbase = (wid & 3) * 32;

    float acc[16][4];
    #pragma unroll
    for (int i = 0; i < 16; i++)
        #pragma unroll
        for (int j = 0; j < 4; j++) acc[i][j] = 0.f;

    for (int k0 = 0; k0 < 512; k0 += 32) {
        load_tile<128>(As, A + (size_t)m0 * 512 + k0, 512);
        load_tile<128>(Bs, W + (size_t)n0 * 512 + k0, 512);
        __syncthreads();
        mma_chunk<4, 4, 0>(As, Bs, mbase, nbase, acc);
        __syncthreads();
    }

    int lane = threadIdx.x & 31, g = lane >> 2, t4 = lane & 3;
    #pragma unroll
    for (int mt = 0; mt < 4; mt++) {
        #pragma unroll
        for (int nt = 0; nt < 4; nt++) {
            int col = n0 + nbase + nt * 8 + t4 * 2;
            int h = col >> 6, d = col & 63;
            int r0 = m0 + mbase + mt * 16 + g;
            int r1 = r0 + 8;
            float* c = acc[mt * 4 + nt];
            *(float2*)&C[(size_t)(((r0 >> 10) * NH + h) * T + (r0 & 1023)) * DK + d] =
                make_float2(c[0], c[1]);
            *(float2*)&C[(size_t)(((r1 >> 10) * NH + h) * T + (r1 & 1023)) * DK + d] =
                make_float2(c[2], c[3]);
        }
    }
}

// =============================================================================
// Output projection (tensor): out = g_Ctx @ w_o^T
// =============================================================================
__global__ void __launch_bounds__(256) tgemm_wo(const float* __restrict__ W,
                                                float* __restrict__ out) {
    __shared__ float As[128 * LDSS];
    __shared__ float Bs[128 * LDSS];

    int m0 = blockIdx.y * 128, n0 = blockIdx.x * 128;
    int wid = threadIdx.x >> 5;
    int mbase = (wid >> 2) * 64, nbase = (wid & 3) * 32;

    float acc[16][4];
    #pragma unroll
    for (int i = 0; i < 16; i++)
        #pragma unroll
        for (int j = 0; j < 4; j++) acc[i][j] = 0.f;

    for (int k0 = 0; k0 < 512; k0 += 32) {
        load_tile<128>(As, g_Ctx + (size_t)m0 * 512 + k0, 512);
        load_tile<128>(Bs, W + (size_t)n0 * 512 + k0, 512);
        __syncthreads();
        mma_chunk<4, 4, 0>(As, Bs, mbase, nbase, acc);
        __syncthreads();
    }

    int lane = threadIdx.x & 31, g = lane >> 2, t4 = lane & 3;
    #pragma unroll
    for (int mt = 0; mt < 4; mt++) {
        #pragma unroll
        for (int nt = 0; nt < 4; nt++) {
            int col = n0 + nbase + nt * 8 + t4 * 2;
            int r0 = m0 + mbase + mt * 16 + g;
            int r1 = r0 + 8;
            float* c = acc[mt * 4 + nt];
            *(float2*)&out[(size_t)r0 * 512 + col] = make_float2(c[0], c[1]);
            *(float2*)&out[(size_t)r1 * 512 + col] = make_float2(c[2], c[3]);
        }
    }
}

// =============================================================================
// M = Q K^T per (b,h) (tensor). 128x128 tiles, K=64.
// =============================================================================
__global__ void __launch_bounds__(256) tqk_kernel() {
    __shared__ float As[128 * LDSS];
    __shared__ float Bs[128 * LDSS];

    int bh = blockIdx.z;
    const float* Qb = g_Q + (size_t)bh * T * DK;
    const float* Kb = g_K + (size_t)bh * T * DK;
    int m0 = blockIdx.y * 128, n0 = blockIdx.x * 128;
    int wid = threadIdx.x >> 5;
    int mbase = (wid >> 2) * 64, nbase = (wid & 3) * 32;

    float acc[16][4];
    #pragma unroll
    for (int i = 0; i < 16; i++)
        #pragma unroll
        for (int j = 0; j < 4; j++) acc[i][j] = 0.f;

    for (int k0 = 0; k0 < 64; k0 += 32) {
        load_tile<128>(As, Qb + (size_t)m0 * DK + k0, DK);
        load_tile<128>(Bs, Kb + (size_t)n0 * DK + k0, DK);
        __syncthreads();
        mma_chunk<4, 4, 0>(As, Bs, mbase, nbase, acc);
        __syncthreads();
    }

    float* Mb = g_M + (size_t)bh * T * T;
    int lane = threadIdx.x & 31, g = lane >> 2, t4 = lane & 3;
    #pragma unroll
    for (int mt = 0; mt < 4; mt++) {
        #pragma unroll
        for (int nt = 0; nt < 4; nt++) {
            int col = n0 + nbase + nt * 8 + t4 * 2;
            int r0 = m0 + mbase + mt * 16 + g;
            int r1 = r0 + 8;
            float* c = acc[mt * 4 + nt];
            *(float2*)&Mb[(size_t)r0 * T + col] = make_float2(c[0], c[1]);
            *(float2*)&Mb[(size_t)r1 * T + col] = make_float2(c[2], c[3]);
        }
    }
}

// =============================================================================
// Ctx = A @ V per (b,h) (tensor). 128x64 tiles, K=1024. V kept k-major in smem.
// =============================================================================
__global__ void __launch_bounds__(256) tav_kernel(const float* __restrict__ A) {
    __shared__ float As[128 * LDSS];
    __shared__ float Vs[32 * 68];

    int bh = blockIdx.y;
    int b = bh >> 3, h = bh & 7;
    const float* Ab = A + (size_t)bh * T * T;
    const float* Vb = g_V + (size_t)bh * T * DK;
    int m0 = blockIdx.x * 128;
    int wid = threadIdx.x >> 5;
    int mbase = (wid >> 1) * 32, nbase = (wid & 1) * 32;

    float acc[8][4];
    #pragma unroll
    for (int i = 0; i < 8; i++)
        #pragma unroll
        for (int j = 0; j < 4; j++) acc[i][j] = 0.f;

    int t = threadIdx.x;
    int vr = t >> 4, vc4 = (t & 15) * 4;

    for (int k0 = 0; k0 < T; k0 += 32) {
        load_tile<128>(As, Ab + (size_t)m0 * T + k0, T);
        #pragma unroll
        for (int i = 0; i < 2; i++) {
            float4 vv = *(const float4*)&Vb[(size_t)(k0 + vr + i * 16) * DK + vc4];
            *(float4*)&Vs[(vr + i * 16) * 68 + vc4] = vv;
        }
        __syncthreads();
        mma_chunk<2, 4, 1>(As, Vs, mbase, nbase, acc);
        __syncthreads();
    }

    int lane = threadIdx.x & 31, g = lane >> 2, t4 = lane & 3;
    #pragma unroll
    for (int mt = 0; mt < 2; mt++) {
        #pragma unroll
        for (int nt = 0; nt < 4; nt++) {
            int d = nbase + nt * 8 + t4 * 2;
            int r0 = m0 + mbase + mt * 16 + g;
            int r1 = r0 + 8;
            float* c = acc[mt * 4 + nt];
            *(float2*)&g_Ctx[(size_t)(b * T + r0) * DM + h * DK + d] = make_float2(c[0], c[1]);
            *(float2*)&g_Ctx[(size_t)(b * T + r1) * DM + h * DK + d] = make_float2(c[2], c[3]);
        }
    }
}

// =============================================================================
// Mt = conv3x3(prev, tw) + tb  (8 -> 8 ch). [round-2 version — known good]
// =============================================================================
__global__ void __launch_bounds__(256) conv_mt(const float* __restrict__ prev,
                                               const float* __restrict__ tw,
                                               const float* __restrict__ tb) {
    __shared__ float s[8][18][66];
    __shared__ float swt[8][9][8];   // [c][t9][o]
    __shared__ float sb[8];

    int b = blockIdx.z;
    int x0 = blockIdx.x * 64;
    int y0 = blockIdx.y * 16;
    int tid = threadIdx.x;
    int tx = tid & 15, ty = tid >> 4;

    for (int e = tid; e < 576; e += 256) {
        int o = e / 72, c = (e % 72) / 9, t9 = e % 9;
        swt[c][t9][o] = tw[e];
    }
    if (tid < 8) sb[tid] = tb[tid];

    for (int e = tid; e < 8 * 18 * 66; e += 256) {
        int c = e / 1188, r = (e % 1188) / 66, cc = e % 66;
        int y = y0 - 1 + r, x = x0 - 1 + cc;
        float val = 0.f;
        if (y >= 0 && y < T && x >= 0 && x < T)
            val = prev[((size_t)(b * 8 + c) * T + y) * T + x];
        s[c][r][cc] = val;
    }
    __syncthreads();

    float2 acc[4][4];
    #pragma unroll
    for (int p = 0; p < 4; p++)
        #pragma unroll
        for (int o2 = 0; o2 < 4; o2++)
            acc[p][o2] = make_float2(sb[o2 * 2], sb[o2 * 2 + 1]);

    int cx = tx * 4;
    #pragma unroll
    for (int c = 0; c < 8; c++) {
        float v[3][6];
        #pragma unroll
        for (int dy = 0; dy < 3; dy++)
            #pragma unroll
            for (int j = 0; j < 6; j++)
                v[dy][j] = s[c][ty + dy][cx + j];
        #pragma unroll
        for (int dy = 0; dy < 3; dy++) {
            #pragma unroll
            for (int dx = 0; dx < 3; dx++) {
                int t9 = dy * 3 + dx;
                float2 w0 = *(float2*)&swt[c][t9][0];
                float2 w1 = *(float2*)&swt[c][t9][2];
                float2 w2 = *(float2*)&swt[c][t9][4];
                float2 w3 = *(float2*)&swt[c][t9][6];
                #pragma unroll
                for (int p = 0; p < 4; p++) {
                    float vv = v[dy][dx + p];
                    float2 vd = make_float2(vv, vv);
                    ffma2(acc[p][0], vd, w0);
                    ffma2(acc[p][1], vd, w1);
                    ffma2(acc[p][2], vd, w2);
                    ffma2(acc[p][3], vd, w3);
                }
            }
        }
    }

    int y = y0 + ty;
    #pragma unroll
    for (int o = 0; o < 8; o++) {
        int o2 = o >> 1;
        float4 ov;
        if (o & 1) ov = make_float4(acc[0][o2].y, acc[1][o2].y, acc[2][o2].y, acc[3][o2].y);
        else       ov = make_float4(acc[0][o2].x, acc[1][o2].x, acc[2][o2].x, acc[3][o2].x);
        *(float4*)&g_Mt[((size_t)(b * 8 + o) * T + y) * T + x0 + cx] = ov;
    }
}

// =============================================================================
// Apre = (conv3x3(concat(M, Mt), aw) + ab) / 8, masked. [round-2 version]
// =============================================================================
__global__ void __launch_bounds__(256) conv_ma(const float* __restrict__ aw,
                                               const float* __restrict__ ab,
                                               const int* __restrict__ mask,
                                               float* __restrict__ Apre) {
    __shared__ float s[8][18][66];
    __shared__ float swa[16][9][8];  // [c][t9][o]
    __shared__ float sab[8];

    int b = blockIdx.z;
    int x0 = blockIdx.x * 64;
    int y0 = blockIdx.y * 16;
    int tid = threadIdx.x;
    int tx = tid & 15, ty = tid >> 4;

    for (int e = tid; e < 1152; e += 256) {
        int o = e / 144, c = (e % 144) / 9, t9 = e % 9;
        swa[c][t9][o] = aw[e];
    }
    if (tid < 8) sab[tid] = ab[tid];

    float2 acc[4][4];
    #pragma unroll
    for (int p = 0; p < 4; p++)
        #pragma unroll
        for (int o2 = 0; o2 < 4; o2++)
            acc[p][o2] = make_float2(0.f, 0.f);

    int cx = tx * 4;

    #pragma unroll
    for (int pass = 0; pass < 2; pass++) {
        const float* src = pass ? g_Mt : g_M;
        for (int e = tid; e < 8 * 18 * 66; e += 256) {
            int c = e / 1188, r = (e % 1188) / 66, cc = e % 66;
            int y = y0 - 1 + r, x = x0 - 1 + cc;
            float val = 0.f;
            if (y >= 0 && y < T && x >= 0 && x < T)
                val = src[((size_t)(b * 8 + c) * T + y) * T + x];
            s[c][r][cc] = val;
        }
        __syncthreads();

        #pragma unroll
        for (int c = 0; c < 8; c++) {
            int cw = c + pass * 8;
            float v[3][6];
            #pragma unroll
            for (int dy = 0; dy < 3; dy++)
                #pragma unroll
                for (int j = 0; j < 6; j++)
                    v[dy][j] = s[c][ty + dy][cx + j];
            #pragma unroll
            for (int dy = 0; dy < 3; dy++) {
                #pragma unroll
                for (int dx = 0; dx < 3; dx++) {
                    int t9 = dy * 3 + dx;
                    float2 w0 = *(float2*)&swa[cw][t9][0];
                    float2 w1 = *(float2*)&swa[cw][t9][2];
                    float2 w2 = *(float2*)&swa[cw][t9][4];
                    float2 w3 = *(float2*)&swa[cw][t9][6];
                    #pragma unroll
                    for (int p = 0; p < 4; p++) {
                        float vv = v[dy][dx + p];
                        float2 vd = make_float2(vv, vv);
                        ffma2(acc[p][0], vd, w0);
                        ffma2(acc[p][1], vd, w1);
                        ffma2(acc[p][2], vd, w2);
                        ffma2(acc[p][3], vd, w3);
                    }
                }
            }
        }
        if (pass == 0) __syncthreads();
    }

    int y = y0 + ty;
    int xg = x0 + cx;
    bool mk[4];
    #pragma unroll
    for (int p = 0; p < 4; p++) mk[p] = (mask[b * T + xg + p] == 0);

    #pragma unroll
    for (int o = 0; o < 8; o++) {
        int o2 = o >> 1;
        float r0, r1, r2, r3;
        if (o & 1) { r0 = acc[0][o2].y; r1 = acc[1][o2].y; r2 = acc[2][o2].y; r3 = acc[3][o2].y; }
        else       { r0 = acc[0][o2].x; r1 = acc[1][o2].x; r2 = acc[2][o2].x; r3 = acc[3][o2].x; }
        float bias = sab[o];
        r0 = (r0 + bias) * 0.125f; r1 = (r1 + bias) * 0.125f;
        r2 = (r2 + bias) * 0.125f; r3 = (r3 + bias) * 0.125f;
        if (mk[0]) r0 = -1e9f;
        if (mk[1]) r1 = -1e9f;
        if (mk[2]) r2 = -1e9f;
        if (mk[3]) r3 = -1e9f;
        float4 ov = make_float4(r0, r1, r2, r3);
        *(float4*)&Apre[((size_t)(b * 8 + o) * T + y) * T + xg] = ov;
    }
}

// ---------------- in-place row softmax (rows of 1024) ------------------------
__global__ void __launch_bounds__(256) softmax_kernel(float* __restrict__ A) {
    __shared__ float red[8];
    int row = blockIdx.x;
    float* p = A + (size_t)row * 1024;
    int tid = threadIdx.x;

    float4 v = *(float4*)&p[tid * 4];

    float mx = fmaxf(fmaxf(v.x, v.y), fmaxf(v.z, v.w));
    #pragma unroll
    for (int o = 16; o > 0; o >>= 1) mx = fmaxf(mx, __shfl_xor_sync(~0u, mx, o));
    if ((tid & 31) == 0) red[tid >> 5] = mx;
    __syncthreads();
    mx = red[0];
    #pragma unroll
    for (int i = 1; i < 8; i++) mx = fmaxf(mx, red[i]);
    __syncthreads();

    v.x = __expf(v.x - mx); v.y = __expf(v.y - mx);
    v.z = __expf(v.z - mx); v.w = __expf(v.w - mx);
    float s = v.x + v.y + v.z + v.w;
    #pragma unroll
    for (int o = 16; o > 0; o >>= 1) s += __shfl_xor_sync(~0u, s, o);
    if ((tid & 31) == 0) red[tid >> 5] = s;
    __syncthreads();
    s = 0.f;
    #pragma unroll
    for (int i = 0; i < 8; i++) s += red[i];
    float inv = 1.f / s;

    v.x *= inv; v.y *= inv; v.z *= inv; v.w *= inv;
    *(float4*)&p[tid * 4] = v;
}

// ---------------- launcher ---------------------------------------------------
extern "C" void kernel_launch(void* const* d_in, const int* in_sizes, int n_in,
                              void* d_out, int out_size) {
    const float* q    = (const float*)d_in[0];
    const float* k    = (const float*)d_in[1];
    const float* v    = (const float*)d_in[2];
    const int*   mask = (const int*)  d_in[3];
    const float* prev = (const float*)d_in[4];
    const float* w_q  = (const float*)d_in[5];
    const float* w_k  = (const float*)d_in[6];
    const float* w_v  = (const float*)d_in[7];
    const float* w_o  = (const float*)d_in[8];
    const float* tw   = (const float*)d_in[9];
    const float* tb   = (const float*)d_in[10];
    const float* aw   = (const float*)d_in[11];
    const float* ab   = (const float*)d_in[12];

    float* out  = (float*)d_out;
    float* Aout = out + (size_t)B * T * DM;

    // projections (tensor, fused 3-way launch)
    tgemm_qkv<<<dim3(DM / 128, (B * T) / 128, 3), 256>>>(q, k, v, w_q, w_k, w_v);

    // Mt = conv(prev)
    conv_mt<<<dim3(T / 64, T / 16, B), 256>>>(prev, tw, tb);

    // M = Q K^T (tensor)
    tqk_kernel<<<dim3(T / 128, T / 128, B * NH), 256>>>();

    // Apre (scaled, masked) -> d_out A region
    conv_ma<<<dim3(T / 64, T / 16, B), 256>>>(aw, ab, mask, Aout);

    // softmax in place
    softmax_kernel<<<B * NH * T, 256>>>(Aout);

    // Ctx = A @ V (tensor)
    tav_kernel<<<dim3(T / 128, B * NH), 256>>>(Aout);

    // out = Ctx @ w_o^T (tensor)
    tgemm_wo<<<dim3(DM / 128, (B * T) / 128), 256>>>(w_o, out);
}

// round 10
// speedup vs baseline: 1.6902x; 1.0238x over previous
#include <cuda_runtime.h>
#include <cstdint>

#define B  4
#define T  1024
#define DM 512
#define NH 8
#define DK 64

// ---------------- scratch (device globals; no allocs allowed) ----------------
__device__ float g_Q[B * NH * T * DK];
__device__ float g_K[B * NH * T * DK];
__device__ float g_V[B * NH * T * DK];
__device__ float g_M[(size_t)B * NH * T * T];
__device__ float g_Mt[(size_t)B * NH * T * T];
__device__ float g_Ctx[B * T * DM];

// packed f32x2 FMA (PTX-only) — used by the conv kernels
union F2U { float2 f; unsigned long long u; };
__device__ __forceinline__ void ffma2(float2& c, float2 a, float2 b) {
    F2U A, Bv, C;
    A.f = a; Bv.f = b; C.f = c;
    asm("fma.rn.f32x2 %0, %1, %2, %0;" : "+l"(C.u) : "l"(A.u), "l"(Bv.u));
    c = C.f;
}

// =============================================================================
// Tensor-core building blocks: split-TF32 (3xTF32) m16n8k8 MMA
// =============================================================================
__device__ __forceinline__ void split_tf32(float x, uint32_t& hi, uint32_t& lo) {
    asm("cvt.rna.tf32.f32 %0, %1;" : "=r"(hi) : "f"(x));
    float l = x - __uint_as_float(hi);
    asm("cvt.rna.tf32.f32 %0, %1;" : "=r"(lo) : "f"(l));
}

__device__ __forceinline__ void mma_tf32(float* c, const uint32_t* a, const uint32_t* b) {
    asm("mma.sync.aligned.m16n8k8.row.col.f32.tf32.tf32.f32 "
        "{%0,%1,%2,%3}, {%4,%5,%6,%7}, {%8,%9}, {%0,%1,%2,%3};"
        : "+f"(c[0]), "+f"(c[1]), "+f"(c[2]), "+f"(c[3])
        : "r"(a[0]), "r"(a[1]), "r"(a[2]), "r"(a[3]), "r"(b[0]), "r"(b[1]));
}

#define LDSS 36   // smem row stride (floats) for 32-wide k tiles (+4 pad)

// Load a ROWS x 32 tile (row-major, leading dim ld) into smem [row][k] w/ stride LDSS
template<int ROWS>
__device__ __forceinline__ void load_tile(float* S, const float* src, int ld) {
    int t = threadIdx.x;
    int r = t >> 3, c4 = (t & 7) * 4;
    #pragma unroll
    for (int i = 0; i < ROWS / 32; i++) {
        float4 v = *(const float4*)&src[(size_t)(r + i * 32) * ld + c4];
        *(float4*)&S[(r + i * 32) * LDSS + c4] = v;
    }
}

// One 32-deep k-chunk of 3xTF32 MMAs.
// A smem: [m][k] stride LDSS. B smem: if BK==0: [n][k] stride LDSS; if BK==1: [k][n] stride 68.
template<int MT, int NT, int BK>
__device__ __forceinline__ void mma_chunk(const float* As, const float* Bs,
                                          int mbase, int nbase, float acc[][4]) {
    int lane = threadIdx.x & 31;
    int g = lane >> 2, t4 = lane & 3;
    #pragma unroll
    for (int k8 = 0; k8 < 4; k8++) {
        const int k0 = k8 * 8;
        uint32_t bhi[NT][2], blo[NT][2];
        #pragma unroll
        for (int nt = 0; nt < NT; nt++) {
            float b0, b1;
            if (BK == 0) {
                const float* bp = Bs + (nbase + nt * 8 + g) * LDSS + k0 + t4;
                b0 = bp[0]; b1 = bp[4];
            } else {
                const float* bp = Bs + (k0 + t4) * 68 + nbase + nt * 8 + g;
                b0 = bp[0]; b1 = bp[4 * 68];
            }
            split_tf32(b0, bhi[nt][0], blo[nt][0]);
            split_tf32(b1, bhi[nt][1], blo[nt][1]);
        }
        #pragma unroll
        for (int mt = 0; mt < MT; mt++) {
            const float* ap = As + (mbase + mt * 16 + g) * LDSS + k0 + t4;
            uint32_t ahi[4], alo[4];
            split_tf32(ap[0],             ahi[0], alo[0]);
            split_tf32(ap[8 * LDSS],      ahi[1], alo[1]);
            split_tf32(ap[4],             ahi[2], alo[2]);
            split_tf32(ap[8 * LDSS + 4],  ahi[3], alo[3]);
            #pragma unroll
            for (int nt = 0; nt < NT; nt++) {
                float* c = acc[mt * NT + nt];
                mma_tf32(c, ahi, bhi[nt]);
                mma_tf32(c, ahi, blo[nt]);
                mma_tf32(c, alo, bhi[nt]);
            }
        }
    }
}

// =============================================================================
// QKV projections (tensor): C = X @ W^T, scatter to (B,H,T,DK). 128x128 tiles.
// =============================================================================
__global__ void __launch_bounds__(256) tgemm_qkv(const float* __restrict__ q,
                                                 const float* __restrict__ k,
                                                 const float* __restrict__ v,
                                                 const float* __restrict__ w_q,
                                                 const float* __restrict__ w_k,
                                                 const float* __restrict__ w_v) {
    __shared__ float As[128 * LDSS];
    __shared__ float Bs[128 * LDSS];

    int z = blockIdx.z;
    const float* A = (z == 0) ? q : (z == 1) ? k : v;
    const float* W = (z == 0) ? w_q : (z == 1) ? w_k : w_v;
    float* C = (z == 0) ? g_Q : (z == 1) ? g_K : g_V;

    int m0 = blockIdx.y * 128, n0 = blockIdx.x * 128;
    int wid = threadIdx.x >> 5;
    int mbase = (wid >> 2) * 64, nbase = (wid & 3) * 32;

    float acc[16][4];
    #pragma unroll
    for (int i = 0; i < 16; i++)
        #pragma unroll
        for (int j = 0; j < 4; j++) acc[i][j] = 0.f;

    for (int k0 = 0; k0 < 512; k0 += 32) {
        load_tile<128>(As, A + (size_t)m0 * 512 + k0, 512);
        load_tile<128>(Bs, W + (size_t)n0 * 512 + k0, 512);
        __syncthreads();
        mma_chunk<4, 4, 0>(As, Bs, mbase, nbase, acc);
        __syncthreads();
    }

    int lane = threadIdx.x & 31, g = lane >> 2, t4 = lane & 3;
    #pragma unroll
    for (int mt = 0; mt < 4; mt++) {
        #pragma unroll
        for (int nt = 0; nt < 4; nt++) {
            int col = n0 + nbase + nt * 8 + t4 * 2;
            int h = col >> 6, d = col & 63;
            int r0 = m0 + mbase + mt * 16 + g;
            int r1 = r0 + 8;
            float* c = acc[mt * 4 + nt];
            *(float2*)&C[(size_t)(((r0 >> 10) * NH + h) * T + (r0 & 1023)) * DK + d] =
                make_float2(c[0], c[1]);
            *(float2*)&C[(size_t)(((r1 >> 10) * NH + h) * T + (r1 & 1023)) * DK + d] =
                make_float2(c[2], c[3]);
        }
    }
}

// =============================================================================
// Output projection (tensor): out = g_Ctx @ w_o^T
// =============================================================================
__global__ void __launch_bounds__(256) tgemm_wo(const float* __restrict__ W,
                                                float* __restrict__ out) {
    __shared__ float As[128 * LDSS];
    __shared__ float Bs[128 * LDSS];

    int m0 = blockIdx.y * 128, n0 = blockIdx.x * 128;
    int wid = threadIdx.x >> 5;
    int mbase = (wid >> 2) * 64, nbase = (wid & 3) * 32;

    float acc[16][4];
    #pragma unroll
    for (int i = 0; i < 16; i++)
        #pragma unroll
        for (int j = 0; j < 4; j++) acc[i][j] = 0.f;

    for (int k0 = 0; k0 < 512; k0 += 32) {
        load_tile<128>(As, g_Ctx + (size_t)m0 * 512 + k0, 512);
        load_tile<128>(Bs, W + (size_t)n0 * 512 + k0, 512);
        __syncthreads();
        mma_chunk<4, 4, 0>(As, Bs, mbase, nbase, acc);
        __syncthreads();
    }

    int lane = threadIdx.x & 31, g = lane >> 2, t4 = lane & 3;
    #pragma unroll
    for (int mt = 0; mt < 4; mt++) {
        #pragma unroll
        for (int nt = 0; nt < 4; nt++) {
            int col = n0 + nbase + nt * 8 + t4 * 2;
            int r0 = m0 + mbase + mt * 16 + g;
            int r1 = r0 + 8;
            float* c = acc[mt * 4 + nt];
            *(float2*)&out[(size_t)r0 * 512 + col] = make_float2(c[0], c[1]);
            *(float2*)&out[(size_t)r1 * 512 + col] = make_float2(c[2], c[3]);
        }
    }
}

// =============================================================================
// M = Q K^T per (b,h) (tensor). 128x128 tiles, K=64.
// =============================================================================
__global__ void __launch_bounds__(256) tqk_kernel() {
    __shared__ float As[128 * LDSS];
    __shared__ float Bs[128 * LDSS];

    int bh = blockIdx.z;
    const float* Qb = g_Q + (size_t)bh * T * DK;
    const float* Kb = g_K + (size_t)bh * T * DK;
    int m0 = blockIdx.y * 128, n0 = blockIdx.x * 128;
    int wid = threadIdx.x >> 5;
    int mbase = (wid >> 2) * 64, nbase = (wid & 3) * 32;

    float acc[16][4];
    #pragma unroll
    for (int i = 0; i < 16; i++)
        #pragma unroll
        for (int j = 0; j < 4; j++) acc[i][j] = 0.f;

    for (int k0 = 0; k0 < 64; k0 += 32) {
        load_tile<128>(As, Qb + (size_t)m0 * DK + k0, DK);
        load_tile<128>(Bs, Kb + (size_t)n0 * DK + k0, DK);
        __syncthreads();
        mma_chunk<4, 4, 0>(As, Bs, mbase, nbase, acc);
        __syncthreads();
    }

    float* Mb = g_M + (size_t)bh * T * T;
    int lane = threadIdx.x & 31, g = lane >> 2, t4 = lane & 3;
    #pragma unroll
    for (int mt = 0; mt < 4; mt++) {
        #pragma unroll
        for (int nt = 0; nt < 4; nt++) {
            int col = n0 + nbase + nt * 8 + t4 * 2;
            int r0 = m0 + mbase + mt * 16 + g;
            int r1 = r0 + 8;
            float* c = acc[mt * 4 + nt];
            *(float2*)&Mb[(size_t)r0 * T + col] = make_float2(c[0], c[1]);
            *(float2*)&Mb[(size_t)r1 * T + col] = make_float2(c[2], c[3]);
        }
    }
}

// =============================================================================
// Ctx = A @ V per (b,h) (tensor). 128x64 tiles, K=1024. V kept k-major in smem.
// =============================================================================
__global__ void __launch_bounds__(256) tav_kernel(const float* __restrict__ A) {
    __shared__ float As[128 * LDSS];
    __shared__ float Vs[32 * 68];

    int bh = blockIdx.y;
    int b = bh >> 3, h = bh & 7;
    const float* Ab = A + (size_t)bh * T * T;
    const float* Vb = g_V + (size_t)bh * T * DK;
    int m0 = blockIdx.x * 128;
    int wid = threadIdx.x >> 5;
    int mbase = (wid >> 1) * 32, nbase = (wid & 1) * 32;

    float acc[8][4];
    #pragma unroll
    for (int i = 0; i < 8; i++)
        #pragma unroll
        for (int j = 0; j < 4; j++) acc[i][j] = 0.f;

    int t = threadIdx.x;
    int vr = t >> 4, vc4 = (t & 15) * 4;

    for (int k0 = 0; k0 < T; k0 += 32) {
        load_tile<128>(As, Ab + (size_t)m0 * T + k0, T);
        #pragma unroll
        for (int i = 0; i < 2; i++) {
            float4 vv = *(const float4*)&Vb[(size_t)(k0 + vr + i * 16) * DK + vc4];
            *(float4*)&Vs[(vr + i * 16) * 68 + vc4] = vv;
        }
        __syncthreads();
        mma_chunk<2, 4, 1>(As, Vs, mbase, nbase, acc);
        __syncthreads();
    }

    int lane = threadIdx.x & 31, g = lane >> 2, t4 = lane & 3;
    #pragma unroll
    for (int mt = 0; mt < 2; mt++) {
        #pragma unroll
        for (int nt = 0; nt < 4; nt++) {
            int d = nbase + nt * 8 + t4 * 2;
            int r0 = m0 + mbase + mt * 16 + g;
            int r1 = r0 + 8;
            float* c = acc[mt * 4 + nt];
            *(float2*)&g_Ctx[(size_t)(b * T + r0) * DM + h * DK + d] = make_float2(c[0], c[1]);
            *(float2*)&g_Ctx[(size_t)(b * T + r1) * DM + h * DK + d] = make_float2(c[2], c[3]);
        }
    }
}

// =============================================================================
// Mt = conv3x3(prev, tw) + tb  (8 -> 8 ch). Round-2 inner loop; 4 CTAs/SM.
// =============================================================================
__global__ void __launch_bounds__(256, 4) conv_mt(const float* __restrict__ prev,
                                                  const float* __restrict__ tw,
                                                  const float* __restrict__ tb) {
    __shared__ float s[8][18][66];
    __shared__ float swt[8][9][8];   // [c][t9][o]
    __shared__ float sb[8];

    int b = blockIdx.z;
    int x0 = blockIdx.x * 64;
    int y0 = blockIdx.y * 16;
    int tid = threadIdx.x;
    int tx = tid & 15, ty = tid >> 4;

    for (int e = tid; e < 576; e += 256) {
        int o = e / 72, c = (e % 72) / 9, t9 = e % 9;
        swt[c][t9][o] = tw[e];
    }
    if (tid < 8) sb[tid] = tb[tid];

    for (int e = tid; e < 8 * 18 * 66; e += 256) {
        int c = e / 1188, r = (e % 1188) / 66, cc = e % 66;
        int y = y0 - 1 + r, x = x0 - 1 + cc;
        float val = 0.f;
        if (y >= 0 && y < T && x >= 0 && x < T)
            val = prev[((size_t)(b * 8 + c) * T + y) * T + x];
        s[c][r][cc] = val;
    }
    __syncthreads();

    float2 acc[4][4];
    #pragma unroll
    for (int p = 0; p < 4; p++)
        #pragma unroll
        for (int o2 = 0; o2 < 4; o2++)
            acc[p][o2] = make_float2(sb[o2 * 2], sb[o2 * 2 + 1]);

    int cx = tx * 4;
    #pragma unroll
    for (int c = 0; c < 8; c++) {
        float v[3][6];
        #pragma unroll
        for (int dy = 0; dy < 3; dy++)
            #pragma unroll
            for (int j = 0; j < 6; j++)
                v[dy][j] = s[c][ty + dy][cx + j];
        #pragma unroll
        for (int dy = 0; dy < 3; dy++) {
            #pragma unroll
            for (int dx = 0; dx < 3; dx++) {
                int t9 = dy * 3 + dx;
                float2 w0 = *(float2*)&swt[c][t9][0];
                float2 w1 = *(float2*)&swt[c][t9][2];
                float2 w2 = *(float2*)&swt[c][t9][4];
                float2 w3 = *(float2*)&swt[c][t9][6];
                #pragma unroll
                for (int p = 0; p < 4; p++) {
                    float vv = v[dy][dx + p];
                    float2 vd = make_float2(vv, vv);
                    ffma2(acc[p][0], vd, w0);
                    ffma2(acc[p][1], vd, w1);
                    ffma2(acc[p][2], vd, w2);
                    ffma2(acc[p][3], vd, w3);
                }
            }
        }
    }

    int y = y0 + ty;
    #pragma unroll
    for (int o = 0; o < 8; o++) {
        int o2 = o >> 1;
        float4 ov;
        if (o & 1) ov = make_float4(acc[0][o2].y, acc[1][o2].y, acc[2][o2].y, acc[3][o2].y);
        else       ov = make_float4(acc[0][o2].x, acc[1][o2].x, acc[2][o2].x, acc[3][o2].x);
        *(float4*)&g_Mt[((size_t)(b * 8 + o) * T + y) * T + x0 + cx] = ov;
    }
}

// =============================================================================
// Apre = (conv3x3(concat(M, Mt), aw) + ab) / 8, masked. Round-2 inner loop; 4 CTAs/SM.
// =============================================================================
__global__ void __launch_bounds__(256, 4) conv_ma(const float* __restrict__ aw,
                                                  const float* __restrict__ ab,
                                                  const int* __restrict__ mask,
                                                  float* __restrict__ Apre) {
    __shared__ float s[8][18][66];
    __shared__ float swa[16][9][8];  // [c][t9][o]
    __shared__ float sab[8];

    int b = blockIdx.z;
    int x0 = blockIdx.x * 64;
    int y0 = blockIdx.y * 16;
    int tid = threadIdx.x;
    int tx = tid & 15, ty = tid >> 4;

    for (int e = tid; e < 1152; e += 256) {
        int o = e / 144, c = (e % 144) / 9, t9 = e % 9;
        swa[c][t9][o] = aw[e];
    }
    if (tid < 8) sab[tid] = ab[tid];

    float2 acc[4][4];
    #pragma unroll
    for (int p = 0; p < 4; p++)
        #pragma unroll
        for (int o2 = 0; o2 < 4; o2++)
            acc[p][o2] = make_float2(0.f, 0.f);

    int cx = tx * 4;

    #pragma unroll
    for (int pass = 0; pass < 2; pass++) {
        const float* src = pass ? g_Mt : g_M;
        for (int e = tid; e < 8 * 18 * 66; e += 256) {
            int c = e / 1188, r = (e % 1188) / 66, cc = e % 66;
            int y = y0 - 1 + r, x = x0 - 1 + cc;
            float val = 0.f;
            if (y >= 0 && y < T && x >= 0 && x < T)
                val = src[((size_t)(b * 8 + c) * T + y) * T + x];
            s[c][r][cc] = val;
        }
        __syncthreads();

        #pragma unroll
        for (int c = 0; c < 8; c++) {
            int cw = c + pass * 8;
            float v[3][6];
            #pragma unroll
            for (int dy = 0; dy < 3; dy++)
                #pragma unroll
                for (int j = 0; j < 6; j++)
                    v[dy][j] = s[c][ty + dy][cx + j];
            #pragma unroll
            for (int dy = 0; dy < 3; dy++) {
                #pragma unroll
                for (int dx = 0; dx < 3; dx++) {
                    int t9 = dy * 3 + dx;
                    float2 w0 = *(float2*)&swa[cw][t9][0];
                    float2 w1 = *(float2*)&swa[cw][t9][2];
                    float2 w2 = *(float2*)&swa[cw][t9][4];
                    float2 w3 = *(float2*)&swa[cw][t9][6];
                    #pragma unroll
                    for (int p = 0; p < 4; p++) {
                        float vv = v[dy][dx + p];
                        float2 vd = make_float2(vv, vv);
                        ffma2(acc[p][0], vd, w0);
                        ffma2(acc[p][1], vd, w1);
                        ffma2(acc[p][2], vd, w2);
                        ffma2(acc[p][3], vd, w3);
                    }
                }
            }
        }
        if (pass == 0) __syncthreads();
    }

    int y = y0 + ty;
    int xg = x0 + cx;
    bool mk[4];
    #pragma unroll
    for (int p = 0; p < 4; p++) mk[p] = (mask[b * T + xg + p] == 0);

    #pragma unroll
    for (int o = 0; o < 8; o++) {
        int o2 = o >> 1;
        float r0, r1, r2, r3;
        if (o & 1) { r0 = acc[0][o2].y; r1 = acc[1][o2].y; r2 = acc[2][o2].y; r3 = acc[3][o2].y; }
        else       { r0 = acc[0][o2].x; r1 = acc[1][o2].x; r2 = acc[2][o2].x; r3 = acc[3][o2].x; }
        float bias = sab[o];
        r0 = (r0 + bias) * 0.125f; r1 = (r1 + bias) * 0.125f;
        r2 = (r2 + bias) * 0.125f; r3 = (r3 + bias) * 0.125f;
        if (mk[0]) r0 = -1e9f;
        if (mk[1]) r1 = -1e9f;
        if (mk[2]) r2 = -1e9f;
        if (mk[3]) r3 = -1e9f;
        float4 ov = make_float4(r0, r1, r2, r3);
        *(float4*)&Apre[((size_t)(b * 8 + o) * T + y) * T + xg] = ov;
    }
}

// ---------------- warp-per-row softmax (rows of 1024), in place ---------------
__global__ void __launch_bounds__(256) softmax_kernel(float* __restrict__ A) {
    int row = blockIdx.x * 8 + (threadIdx.x >> 5);
    int lane = threadIdx.x & 31;
    float* p = A + (size_t)row * 1024;

    float4 v[8];
    #pragma unroll
    for (int j = 0; j < 8; j++) v[j] = *(float4*)&p[(j * 32 + lane) * 4];

    float mx = -3.4e38f;
    #pragma unroll
    for (int j = 0; j < 8; j++)
        mx = fmaxf(mx, fmaxf(fmaxf(v[j].x, v[j].y), fmaxf(v[j].z, v[j].w)));
    #pragma unroll
    for (int o = 16; o > 0; o >>= 1) mx = fmaxf(mx, __shfl_xor_sync(~0u, mx, o));

    float s = 0.f;
    #pragma unroll
    for (int j = 0; j < 8; j++) {
        v[j].x = __expf(v[j].x - mx); v[j].y = __expf(v[j].y - mx);
        v[j].z = __expf(v[j].z - mx); v[j].w = __expf(v[j].w - mx);
        s += v[j].x + v[j].y + v[j].z + v[j].w;
    }
    #pragma unroll
    for (int o = 16; o > 0; o >>= 1) s += __shfl_xor_sync(~0u, s, o);
    float inv = 1.f / s;

    #pragma unroll
    for (int j = 0; j < 8; j++) {
        v[j].x *= inv; v[j].y *= inv; v[j].z *= inv; v[j].w *= inv;
        *(float4*)&p[(j * 32 + lane) * 4] = v[j];
    }
}

// ---------------- launcher ---------------------------------------------------
extern "C" void kernel_launch(void* const* d_in, const int* in_sizes, int n_in,
                              void* d_out, int out_size) {
    const float* q    = (const float*)d_in[0];
    const float* k    = (const float*)d_in[1];
    const float* v    = (const float*)d_in[2];
    const int*   mask = (const int*)  d_in[3];
    const float* prev = (const float*)d_in[4];
    const float* w_q  = (const float*)d_in[5];
    const float* w_k  = (const float*)d_in[6];
    const float* w_v  = (const float*)d_in[7];
    const float* w_o  = (const float*)d_in[8];
    const float* tw   = (const float*)d_in[9];
    const float* tb   = (const float*)d_in[10];
    const float* aw   = (const float*)d_in[11];
    const float* ab   = (const float*)d_in[12];

    float* out  = (float*)d_out;
    float* Aout = out + (size_t)B * T * DM;

    // One-time host-side resources (created on the correctness call, reused
    // under graph capture; only event record/wait are issued per call).
    static cudaStream_t s_side = ([]() {
        cudaStream_t s; cudaStreamCreateWithFlags(&s, cudaStreamNonBlocking); return s;
    })();
    static cudaEvent_t ev_fork = ([]() {
        cudaEvent_t e; cudaEventCreateWithFlags(&e, cudaEventDisableTiming); return e;
    })();
    static cudaEvent_t ev_join = ([]() {
        cudaEvent_t e; cudaEventCreateWithFlags(&e, cudaEventDisableTiming); return e;
    })();

    // ---- fork: conv_mt (depends only on prev) runs on side stream ----------
    cudaEventRecord(ev_fork, 0);
    cudaStreamWaitEvent(s_side, ev_fork, 0);
    conv_mt<<<dim3(T / 64, T / 16, B), 256, 0, s_side>>>(prev, tw, tb);
    cudaEventRecord(ev_join, s_side);

    // ---- main chain on default stream (overlaps with conv_mt) --------------
    tgemm_qkv<<<dim3(DM / 128, (B * T) / 128, 3), 256>>>(q, k, v, w_q, w_k, w_v);
    tqk_kernel<<<dim3(T / 128, T / 128, B * NH), 256>>>();

    // ---- join: conv_ma needs both g_M and g_Mt -----------------------------
    cudaStreamWaitEvent(0, ev_join, 0);
    conv_ma<<<dim3(T / 64, T / 16, B), 256>>>(aw, ab, mask, Aout);

    softmax_kernel<<<(B * NH * T) / 8, 256>>>(Aout);
    tav_kernel<<<dim3(T / 128, B * NH), 256>>>(Aout);
    tgemm_wo<<<dim3(DM / 128, (B * T) / 128), 256>>>(w_o, out);
}